// round 12
// baseline (speedup 1.0000x reference)
#include <cuda_runtime.h>
#include <stdint.h>
#include <math.h>

#define T_FRAMES   3000
#define F_BINS     201
#define FROW       402                  // floats per frame
#define BATCH      32
#define CHUNK      334
#define CHUNKS     9                    // grid 288 <= 296 (2 blocks/SM, one wave)
#define NTHREADS   224
#define NWARPS     7
#define EPS_F      1e-5f
#define LOG10_2    0.30102999566398f
#define GROUP_FLOATS (30 * FROW)        // 12060
#define GROUP_BYTES  (GROUP_FLOATS * 4) // 48240
#define GROUP_CHUNKS (GROUP_BYTES / 16) // 3015
#define SMEM_BYTES   (2 * GROUP_BYTES + 5 * NTHREADS * 8)  // 105440

__device__ __forceinline__ void cp_async16(uint32_t s, const float* g) {
  asm volatile("cp.async.ca.shared.global [%0], [%1], 16;\n" :: "r"(s), "l"(g));
}
#define CP_COMMIT() asm volatile("cp.async.commit_group;\n" ::: "memory")
#define CP_WAIT1()  asm volatile("cp.async.wait_group 1;\n" ::: "memory")
#define CP_WAIT0()  asm volatile("cp.async.wait_group 0;\n" ::: "memory")

// Fill one group buffer (30 frames, contiguous 48240 B) cooperatively:
// thread tid loads chunks tid, tid+224, ... (16 B each). Per-chunk clamp vs
// the end of x keeps tail prefetches safe (clamped data only feeds frames
// >= T_FRAMES, whose outputs are masked).
#define FILL(DST_U32, GB_PTR)                                                    \
  do {                                                                           \
    const float* gb_ = (GB_PTR);                                                 \
    _Pragma("unroll")                                                            \
    for (int i_ = 0; i_ < 14; i_++) {                                            \
      const int ch_ = tid + i_ * NTHREADS;                                       \
      if (ch_ < GROUP_CHUNKS) {                                                  \
        const float* p_ = gb_ + 4 * ch_;                                         \
        if (p_ > xlim) p_ = xlim;                                                \
        cp_async16((DST_U32) + 16 * ch_, p_);                                    \
      }                                                                          \
    }                                                                            \
    CP_COMMIT();                                                                 \
  } while (0)

// Per-frame scan math. J compile-time (unrolled) -> ring indices are fixed
// registers. Inactive threads masked by L10m==0 (FFMA self-zeroes). T0CHK
// (compile-time) guards the t==0 case; only warm frame 0 enables it.
#define FRAME_MATH(J, RC10, RC30, RC30LM, DO_SUB, T0CHK, OUTV)                   \
  do {                                                                           \
    const float2 xv = *(const float2*)(sbuf + (J) * FROW + foff);                \
    const float s_t = fmaf(xv.y, xv.y, xv.x * xv.x) * Cf;                        \
    float we_t = fmaf(sum_s, (RC10), EPS_F);                                     \
    if (T0CHK) we_t = t0block ? EPS_F : we_t;                                    \
    const float lw2_t = __log2f(we_t);                                           \
    {                                                                            \
      const float am = sum_we * (RC30);                                          \
      OUTV = fmaf(__log2f(am), L10m, -(sum_lw2 * (RC30LM)));                     \
      if (T0CHK) OUTV = t0block ? 0.f : OUTV;                                    \
    }                                                                            \
    if (DO_SUB) {                                                                \
      const float we_old = ring_w[(J) % 30];                                     \
      sum_we  += we_t - we_old;                                                  \
      sum_lw2 += lw2_t - __log2f(we_old);                                        \
    } else {                                                                     \
      sum_we  += we_t;                                                           \
      sum_lw2 += lw2_t;                                                          \
    }                                                                            \
    ring_w[(J) % 30] = we_t;                                                     \
    sum_s += s_t - ring_s[(J) % 10];                                             \
    ring_s[(J) % 10] = s_t;                                                      \
  } while (0)

// Ten steady frames (5 pairs), contribs stored as one STS.64 per pair.
#define SUB10_STEADY(J0)                                                         \
  do {                                                                           \
    _Pragma("unroll")                                                            \
    for (int p_ = 0; p_ < 5; p_++) {                                             \
      float cA_, cB_;                                                            \
      FRAME_MATH((J0) + 2 * p_,     0.1f, (1.0f/30.0f), rc30Lm, true, false, cA_); \
      FRAME_MATH((J0) + 2 * p_ + 1, 0.1f, (1.0f/30.0f), rc30Lm, true, false, cB_); \
      if (emit) buf2[p_ * NTHREADS + tid] = make_float2(cA_, cB_);               \
    }                                                                            \
  } while (0)

// Ten warm frames with exact ramp divisors (compile-time after unroll),
// DO_SUB=false (rings hold zeros).
#define SUB10_WARM(J0)                                                           \
  do {                                                                           \
    _Pragma("unroll")                                                            \
    for (int p_ = 0; p_ < 5; p_++) {                                             \
      const int jA_ = (J0) + 2 * p_, jB_ = jA_ + 1;                              \
      const float rc10A_ = 1.0f / (float)((jA_ < 1) ? 1 : (jA_ > 10 ? 10 : jA_));\
      const float rc30A_ = 1.0f / (float)((jA_ < 1) ? 1 : jA_);                  \
      const float rc10B_ = 1.0f / (float)((jB_ > 10) ? 10 : jB_);                \
      const float rc30B_ = 1.0f / (float)jB_;                                    \
      float cA_, cB_;                                                            \
      FRAME_MATH(jA_, rc10A_, rc30A_, rc30A_ * L10m, false, (jA_ == 0), cA_);    \
      FRAME_MATH(jB_, rc10B_, rc30B_, rc30B_ * L10m, false, false, cB_);         \
      if (emit) buf2[p_ * NTHREADS + tid] = make_float2(cA_, cB_);               \
    }                                                                            \
  } while (0)

// Reduce one sub-group's 5 contrib pairs (warps 0-4, one pair each).
// Writes masked to [chunk_start, chunk_end).
#define REDUCE5(TB)                                                              \
  do {                                                                           \
    if (warp < 5) {                                                              \
      float vx_ = 0.f, vy_ = 0.f;                                                \
      _Pragma("unroll")                                                          \
      for (int i_ = 0; i_ < 7; i_++) {                                           \
        const float2 u_ = buf2[warp * NTHREADS + lane + 32 * i_];                \
        vx_ += u_.x; vy_ += u_.y;                                                \
      }                                                                          \
      _Pragma("unroll")                                                          \
      for (int o_ = 16; o_ > 0; o_ >>= 1) {                                      \
        vx_ += __shfl_xor_sync(0xffffffffu, vx_, o_);                            \
        vy_ += __shfl_xor_sync(0xffffffffu, vy_, o_);                            \
      }                                                                          \
      if (lane == 0) {                                                           \
        const int tA_ = (TB) + 2 * warp;                                         \
        if (tA_ >= chunk_start && tA_ < chunk_end)                               \
          out[(size_t)b * T_FRAMES + tA_] = vx_;                                 \
        if (tA_ + 1 >= chunk_start && tA_ + 1 < chunk_end)                       \
          out[(size_t)b * T_FRAMES + tA_ + 1] = vy_;                             \
      }                                                                          \
    }                                                                            \
  } while (0)

// One 30-frame group. Barriers are block-uniform (emit is uniform). The
// CP_WAIT0 before the 3rd sub's barrier + that barrier = cross-thread
// visibility point for the NEXT group's buffer (filled one group ago).
#define GROUP_BODY(SUBM, TB)                                                     \
  do {                                                                           \
    SUBM(0);  __syncthreads(); if (emit) REDUCE5(TB);        __syncthreads();    \
    SUBM(10); __syncthreads(); if (emit) REDUCE5((TB) + 10); __syncthreads();    \
    SUBM(20); CP_WAIT0();                                                        \
    __syncthreads();           if (emit) REDUCE5((TB) + 20); __syncthreads();    \
  } while (0)

__global__ __launch_bounds__(NTHREADS)
void ltsf_kernel(const float* __restrict__ x, float* __restrict__ out,
                 const float cA) {
  extern __shared__ float dsm[];
  float*  stage = dsm;                               // 2 group buffers
  float2* buf2  = (float2*)(dsm + 2 * GROUP_FLOATS); // 5 contrib pairs

  const int unit = blockIdx.x;
  const int b = unit / CHUNKS;
  const int c = unit % CHUNKS;
  const int chunk_start = c * CHUNK;
  const int chunk_end = min(chunk_start + CHUNK, T_FRAMES);
  // >= 40 frames of halo, rounded DOWN to even (keeps group bases 16B-aligned)
  const int t_begin = (c == 0) ? 0 : ((chunk_start - 40) & ~1);
  const bool t0block = (c == 0);

  const int tid  = threadIdx.x;
  const int f    = tid;
  const bool active = (f < F_BINS);
  const int lane = tid & 31;
  const int warp = tid >> 5;

  // per-bin scale: interior bins doubled (welch one-sided spectrum)
  const float Cf = (f == 0 || f == F_BINS - 1) ? cA : 2.0f * cA;
  const float L10m   = active ? LOG10_2 : 0.f;  // masks inactive contribs to 0
  const float rc30Lm = L10m * (1.0f / 30.0f);

  const int fsel = active ? f : 0;
  const int foff = 2 * fsel;
  const float* xb   = x + (size_t)b * T_FRAMES * FROW;
  const float* xlim = x + (size_t)BATCH * T_FRAMES * FROW - 4;  // last 16B

  const uint32_t db0 = (uint32_t)__cvta_generic_to_shared(stage);
  const uint32_t db1 = db0 + GROUP_BYTES;

  // register-resident ring buffers (indices compile-time via full unroll)
  float ring_s[10];
  float ring_w[30];
  float sum_s = 0.f, sum_we = 0.f, sum_lw2 = 0.f;
#pragma unroll
  for (int i = 0; i < 10; i++) ring_s[i] = 0.f;
#pragma unroll
  for (int i = 0; i < 30; i++) ring_w[i] = 0.f;

  // ---- prologue: fill both group buffers ----
  FILL(db0, xb + (size_t)t_begin * FROW);
  FILL(db1, xb + (size_t)(t_begin + 30) * FROW);
  CP_WAIT1();          // buffer 0 complete (own copies)
  __syncthreads();     // ... and visible to all threads

  // ---- warm group: frames t_begin..t_begin+29, ramp divisors ----
  {
    const bool emit = t0block;
    const float* sbuf = stage;
    GROUP_BODY(SUB10_WARM, t_begin);
    FILL(db0, xb + (size_t)(t_begin + 60) * FROW);  // refill for group 2
  }

  // ---- steady groups ----
  bool flip = true;  // consume buffer 1 next
  for (int tb = t_begin + 30; tb < chunk_end; tb += 30) {
    const bool emit = (tb + 29 >= chunk_start);  // block-uniform
    const float* sbuf = flip ? (stage + GROUP_FLOATS) : stage;
    GROUP_BODY(SUB10_STEADY, tb);
    FILL(flip ? db1 : db0, xb + (size_t)(tb + 60) * FROW);
    flip = !flip;
  }
}

extern "C" void kernel_launch(void* const* d_in, const int* in_sizes, int n_in,
                              void* d_out, int out_size) {
  (void)in_sizes; (void)n_in; (void)out_size;
  // hamming_sq_sum(25), periodic: sum((0.54 - 0.46*cos(2*pi*k/25))^2)
  double h = 0.0;
  for (int k = 0; k < 25; k++) {
    double w = 0.54 - 0.46 * cos(2.0 * M_PI * (double)k / 25.0);
    h += w * w;
  }
  // fold the /M (spectr) and /SAMPLE_RATE (welch) into one per-bin constant
  const float cA = (float)(h / 16000.0 / 10.0);

  // dynamic smem: 105,440 B per block (2 group buffers + contrib tile)
  cudaFuncSetAttribute(ltsf_kernel,
                       cudaFuncAttributeMaxDynamicSharedMemorySize, SMEM_BYTES);

  const float* x = (const float*)d_in[0];
  float* out = (float*)d_out;
  ltsf_kernel<<<BATCH * CHUNKS, NTHREADS, SMEM_BYTES>>>(x, out, cA);
}

// round 13
// speedup vs baseline: 1.3495x; 1.3495x over previous
#include <cuda_runtime.h>
#include <stdint.h>
#include <math.h>

#define T_FRAMES   3000
#define F_BINS     201
#define FROW       402                  // floats per frame
#define BATCH      32
#define CHUNK      167
#define CHUNKS     18                   // 18*167 = 3006 >= 3000; last chunk short
#define NTHREADS   224
#define NWARPS     7
#define EPS_F      1e-5f
#define LOG10_2    0.30102999566398f
#define SUBF       (10 * FROW)          // floats per 10-frame sub-buffer (4020)
#define SUBB       (SUBF * 4)           // bytes (16080)
#define SUBCH      (SUBB / 16)          // 16B chunks (1005)

__device__ __forceinline__ void cp_async16(uint32_t s, const float* g) {
  asm volatile("cp.async.ca.shared.global [%0], [%1], 16;\n" :: "r"(s), "l"(g));
}
#define CP_COMMIT() asm volatile("cp.async.commit_group;\n" ::: "memory")
#define CP_WAIT0()  asm volatile("cp.async.wait_group 0;\n" ::: "memory")

// Cooperative fill of one 10-frame sub-buffer: 1005 x 16B chunks over 224
// threads (<=5 each). Sub-buffer start frames are even (t_begin even, +10
// steps) so global addresses are 16B-aligned. Per-chunk clamp to the last
// 16B of x keeps tail fills in-bounds (clamped data only reaches frames
// whose outputs are masked).
#define FILL10(DST_U32, SRC_PTR)                                                 \
  do {                                                                           \
    const float* gb_ = (SRC_PTR);                                                \
    _Pragma("unroll")                                                            \
    for (int i_ = 0; i_ < 5; i_++) {                                             \
      const int ch_ = tid + i_ * NTHREADS;                                       \
      if (ch_ < SUBCH) {                                                         \
        const float* p_ = gb_ + 4 * ch_;                                         \
        if (p_ > xlim) p_ = xlim;                                                \
        cp_async16((DST_U32) + 16 * ch_, p_);                                    \
      }                                                                          \
    }                                                                            \
    CP_COMMIT();                                                                 \
  } while (0)

// Per-frame scan math. J (ring index 0..29) and LJ (sub-buffer frame 0..9)
// are compile-time after unroll -> ring regs fixed, LDS offset immediate.
// Inactive threads masked by L10m==0 (FFMA self-zeroes). T0CHK guards t==0.
#define FRAME_MATH(J, LJ, RC10, RC30, RC30LM, DO_SUB, T0CHK, OUTV)               \
  do {                                                                           \
    const float2 xv = *(const float2*)(cur_p + (LJ) * FROW + foff);              \
    const float s_t = fmaf(xv.y, xv.y, xv.x * xv.x) * Cf;                        \
    float we_t = fmaf(sum_s, (RC10), EPS_F);                                     \
    if (T0CHK) we_t = t0block ? EPS_F : we_t;                                    \
    const float lw2_t = __log2f(we_t);                                           \
    {                                                                            \
      const float am = sum_we * (RC30);                                          \
      OUTV = fmaf(__log2f(am), L10m, -(sum_lw2 * (RC30LM)));                     \
      if (T0CHK) OUTV = t0block ? 0.f : OUTV;                                    \
    }                                                                            \
    if (DO_SUB) {                                                                \
      const float we_old = ring_w[(J) % 30];                                     \
      sum_we  += we_t - we_old;                                                  \
      sum_lw2 += lw2_t - __log2f(we_old);                                        \
    } else {                                                                     \
      sum_we  += we_t;                                                           \
      sum_lw2 += lw2_t;                                                          \
    }                                                                            \
    ring_w[(J) % 30] = we_t;                                                     \
    sum_s += s_t - ring_s[(J) % 10];                                             \
    ring_s[(J) % 10] = s_t;                                                      \
  } while (0)

// Consume 10 steady frames (5 pairs), contrib pairs stored via STS.64.
#define CONSUME_STEADY(J0, ES)                                                   \
  do {                                                                           \
    _Pragma("unroll")                                                            \
    for (int p_ = 0; p_ < 5; p_++) {                                             \
      float cA_, cB_;                                                            \
      FRAME_MATH((J0)+2*p_,   2*p_,   0.1f, (1.0f/30.0f), rc30Lm, true, false, cA_); \
      FRAME_MATH((J0)+2*p_+1, 2*p_+1, 0.1f, (1.0f/30.0f), rc30Lm, true, false, cB_); \
      if (ES) buf2[p_ * NTHREADS + tid] = make_float2(cA_, cB_);                 \
    }                                                                            \
  } while (0)

// Consume 10 warm frames with exact ramp divisors (compile-time), no ring
// subtraction (rings hold zeros).
#define CONSUME_WARM(J0, ES)                                                     \
  do {                                                                           \
    _Pragma("unroll")                                                            \
    for (int p_ = 0; p_ < 5; p_++) {                                             \
      const int jA_ = (J0) + 2 * p_, jB_ = jA_ + 1;                              \
      const float rc10A_ = 1.0f / (float)((jA_ < 1) ? 1 : (jA_ > 10 ? 10 : jA_));\
      const float rc30A_ = 1.0f / (float)((jA_ < 1) ? 1 : jA_);                  \
      const float rc10B_ = 1.0f / (float)((jB_ > 10) ? 10 : jB_);                \
      const float rc30B_ = 1.0f / (float)jB_;                                    \
      float cA_, cB_;                                                            \
      FRAME_MATH(jA_, 2*p_,   rc10A_, rc30A_, rc30A_ * L10m, false, (jA_==0), cA_); \
      FRAME_MATH(jB_, 2*p_+1, rc10B_, rc30B_, rc30B_ * L10m, false, false, cB_); \
      if (ES) buf2[p_ * NTHREADS + tid] = make_float2(cA_, cB_);                 \
    }                                                                            \
  } while (0)

// Reduce 5 contrib pairs (warps 0-4, one pair each), mask writes to
// [chunk_start, chunk_end).
#define REDUCE5(TB)                                                              \
  do {                                                                           \
    if (warp < 5) {                                                              \
      float vx_ = 0.f, vy_ = 0.f;                                                \
      _Pragma("unroll")                                                          \
      for (int i_ = 0; i_ < 7; i_++) {                                           \
        const float2 u_ = buf2[warp * NTHREADS + lane + 32 * i_];                \
        vx_ += u_.x; vy_ += u_.y;                                                \
      }                                                                          \
      _Pragma("unroll")                                                          \
      for (int o_ = 16; o_ > 0; o_ >>= 1) {                                      \
        vx_ += __shfl_xor_sync(0xffffffffu, vx_, o_);                            \
        vy_ += __shfl_xor_sync(0xffffffffu, vy_, o_);                            \
      }                                                                          \
      if (lane == 0) {                                                           \
        const int tA_ = (TB) + 2 * warp;                                         \
        if (tA_ >= chunk_start && tA_ < chunk_end)                               \
          out[(size_t)b * T_FRAMES + tA_] = vx_;                                 \
        if (tA_ + 1 >= chunk_start && tA_ + 1 < chunk_end)                       \
          out[(size_t)b * T_FRAMES + tA_ + 1] = vy_;                             \
      }                                                                          \
    }                                                                            \
  } while (0)

// One sub-group: issue fill for the NEXT sub-buffer (into oth), consume the
// current one, then wait+sync (visibility for next consume AND for buf2),
// reduce, sync, swap buffers. All branches block-uniform.
#define SUBGROUP(CONSUME_M, J0, TS)                                              \
  do {                                                                           \
    const int ts_ = (TS);                                                        \
    const bool es_ = (ts_ + 9 >= chunk_start) && (ts_ < chunk_end);              \
    if (ts_ + 10 < chunk_end)                                                    \
      FILL10(oth_a, xb + (size_t)(ts_ + 10) * FROW);                             \
    CONSUME_M(J0, es_);                                                          \
    CP_WAIT0();                                                                  \
    __syncthreads();                                                             \
    if (es_) REDUCE5(ts_);                                                       \
    __syncthreads();                                                             \
    { float* tp_ = cur_p; cur_p = oth_p; oth_p = tp_;                            \
      const uint32_t ta_ = cur_a; cur_a = oth_a; oth_a = ta_; }                  \
  } while (0)

__global__ __launch_bounds__(NTHREADS, 4)
void ltsf_kernel(const float* __restrict__ x, float* __restrict__ out,
                 const float cA) {
  __shared__ float  stage[2 * SUBF];       // two 10-frame sub-buffers (32.2 KB)
  __shared__ float2 buf2[5 * NTHREADS];    // contrib pairs (9 KB)

  const int unit = blockIdx.x;
  const int b = unit / CHUNKS;
  const int c = unit % CHUNKS;
  const int chunk_start = c * CHUNK;
  const int chunk_end = min(chunk_start + CHUNK, T_FRAMES);
  // >= 40 frames of halo, rounded DOWN to even (16B alignment of sub-buffers)
  const int t_begin = (c == 0) ? 0 : ((chunk_start - 40) & ~1);
  const bool t0block = (c == 0);

  const int tid  = threadIdx.x;
  const int f    = tid;
  const bool active = (f < F_BINS);
  const int lane = tid & 31;
  const int warp = tid >> 5;

  // per-bin scale: interior bins doubled (welch one-sided spectrum)
  const float Cf = (f == 0 || f == F_BINS - 1) ? cA : 2.0f * cA;
  const float L10m   = active ? LOG10_2 : 0.f;  // masks inactive contribs to 0
  const float rc30Lm = L10m * (1.0f / 30.0f);

  const int fsel = active ? f : 0;
  const int foff = 2 * fsel;
  const float* xb   = x + (size_t)b * T_FRAMES * FROW;
  const float* xlim = x + (size_t)BATCH * T_FRAMES * FROW - 4;  // last 16B

  float* cur_p = stage;
  float* oth_p = stage + SUBF;
  uint32_t cur_a = (uint32_t)__cvta_generic_to_shared(stage);
  uint32_t oth_a = cur_a + SUBB;

  // register-resident ring buffers (indices compile-time via full unroll)
  float ring_s[10];
  float ring_w[30];
  float sum_s = 0.f, sum_we = 0.f, sum_lw2 = 0.f;
#pragma unroll
  for (int i = 0; i < 10; i++) ring_s[i] = 0.f;
#pragma unroll
  for (int i = 0; i < 30; i++) ring_w[i] = 0.f;

  // ---- prologue: fill first sub-buffer, make it visible ----
  FILL10(cur_a, xb + (size_t)t_begin * FROW);
  CP_WAIT0();
  __syncthreads();

  // ---- warm group: frames t_begin..t_begin+29, ramp divisors ----
  SUBGROUP(CONSUME_WARM, 0,  t_begin);
  SUBGROUP(CONSUME_WARM, 10, t_begin + 10);
  SUBGROUP(CONSUME_WARM, 20, t_begin + 20);

  // ---- steady groups (sub-groups past chunk_end consume stale smem but
  //      never write: es_ is false there) ----
  for (int tb = t_begin + 30; tb < chunk_end; tb += 30) {
    SUBGROUP(CONSUME_STEADY, 0,  tb);
    SUBGROUP(CONSUME_STEADY, 10, tb + 10);
    SUBGROUP(CONSUME_STEADY, 20, tb + 20);
  }
}

extern "C" void kernel_launch(void* const* d_in, const int* in_sizes, int n_in,
                              void* d_out, int out_size) {
  (void)in_sizes; (void)n_in; (void)out_size;
  // hamming_sq_sum(25), periodic: sum((0.54 - 0.46*cos(2*pi*k/25))^2)
  double h = 0.0;
  for (int k = 0; k < 25; k++) {
    double w = 0.54 - 0.46 * cos(2.0 * M_PI * (double)k / 25.0);
    h += w * w;
  }
  // fold the /M (spectr) and /SAMPLE_RATE (welch) into one per-bin constant
  const float cA = (float)(h / 16000.0 / 10.0);

  const float* x = (const float*)d_in[0];
  float* out = (float*)d_out;
  ltsf_kernel<<<BATCH * CHUNKS, NTHREADS>>>(x, out, cA);
}